// round 3
// baseline (speedup 1.0000x reference)
#include <cuda_runtime.h>
#include <cstdint>
#include <math.h>

#define T_TOK 4096
#define DIMSZ 1024
#define INNER 4096
#define NEXP  8

// ---------------- device scratch (no runtime allocation allowed) ----------------
__device__ float g_Xg[2 * T_TOK * DIMSZ];        // gathered routed inputs   (32 MB)
__device__ float g_H [3 * T_TOK * INNER];        // hidden: routed(2T) + shared(T) (192 MB)
__device__ float g_Og[3 * T_TOK * DIMSZ];        // ffn outputs              (48 MB)
__device__ float g_topw[T_TOK * 2];
__device__ int   g_tope[T_TOK * 2];
__device__ int   g_rows[T_TOK * 2];
__device__ int   g_cnt[NEXP];
__device__ int   g_cur[NEXP];
__device__ int   g_off[NEXP];

// ---------------- helpers ----------------
__device__ __forceinline__ uint32_t f2tf32(float f) {
    uint32_t u;
    asm("cvt.rna.tf32.f32 %0, %1;" : "=r"(u) : "f"(f));
    return u;
}

__device__ __forceinline__ void cpa16(void* smem_dst, const void* gmem_src, bool pred) {
    uint32_t saddr = (uint32_t)__cvta_generic_to_shared(smem_dst);
    int sz = pred ? 16 : 0;
    asm volatile("cp.async.cg.shared.global [%0], [%1], 16, %2;\n"
                 :: "r"(saddr), "l"(gmem_src), "r"(sz));
}

__device__ __forceinline__ float gelu_exact(float v) {
    return 0.5f * v * (1.0f + erff(v * 0.70710678118654752440f));
}

// ---------------- small kernels ----------------
__global__ void k_zero() {
    int i = threadIdx.x;
    if (i < NEXP) { g_cnt[i] = 0; g_cur[i] = 0; }
}

__global__ void k_gate(const float* __restrict__ x, const float* __restrict__ Wg) {
    int t = blockIdx.x * 4 + (threadIdx.x >> 5);
    int lane = threadIdx.x & 31;
    if (t >= T_TOK) return;
    const float* xp = x + (size_t)t * DIMSZ;
    float xr[32];
#pragma unroll
    for (int j = 0; j < 32; j++) xr[j] = xp[j * 32 + lane];
    float s[8];
#pragma unroll
    for (int e = 0; e < 8; e++) {
        const float* wg = Wg + e * DIMSZ;
        float p = 0.f;
#pragma unroll
        for (int j = 0; j < 32; j++) p += xr[j] * wg[j * 32 + lane];
#pragma unroll
        for (int o = 16; o > 0; o >>= 1) p += __shfl_xor_sync(0xffffffffu, p, o);
        s[e] = p;
    }
    if (lane == 0) {
        float m = s[0];
#pragma unroll
        for (int e = 1; e < 8; e++) m = fmaxf(m, s[e]);
        float p[8]; float sum = 0.f;
#pragma unroll
        for (int e = 0; e < 8; e++) { p[e] = expf(s[e] - m); sum += p[e]; }
        float inv = 1.0f / sum;
#pragma unroll
        for (int e = 0; e < 8; e++) p[e] *= inv;
        int e0 = 0; float w0 = p[0];
#pragma unroll
        for (int e = 1; e < 8; e++) if (p[e] > w0) { w0 = p[e]; e0 = e; }
        int e1 = -1; float w1 = -1.f;
#pragma unroll
        for (int e = 0; e < 8; e++) if (e != e0 && p[e] > w1) { w1 = p[e]; e1 = e; }
        g_topw[t * 2] = w0;     g_tope[t * 2] = e0;
        g_topw[t * 2 + 1] = w1; g_tope[t * 2 + 1] = e1;
        atomicAdd(&g_cnt[e0], 1);
        atomicAdd(&g_cnt[e1], 1);
    }
}

__global__ void k_scan() {
    if (threadIdx.x == 0) {
        int acc = 0;
        for (int e = 0; e < NEXP; e++) { g_off[e] = acc; acc += g_cnt[e]; }
    }
}

__global__ void k_gather(const float* __restrict__ x) {
    int t = blockIdx.x;
    __shared__ int rs[2];
    if (threadIdx.x == 0) {
#pragma unroll
        for (int k = 0; k < 2; k++) {
            int e = g_tope[t * 2 + k];
            int slot = atomicAdd(&g_cur[e], 1);
            int r = g_off[e] + slot;
            g_rows[t * 2 + k] = r;
            rs[k] = r;
        }
    }
    __syncthreads();
    const float4* xp = (const float4*)(x + (size_t)t * DIMSZ);
    float4 v0 = xp[threadIdx.x];
    float4 v1 = xp[threadIdx.x + 128];
    float4* d0 = (float4*)(g_Xg + (size_t)rs[0] * DIMSZ);
    float4* d1 = (float4*)(g_Xg + (size_t)rs[1] * DIMSZ);
    d0[threadIdx.x] = v0; d0[threadIdx.x + 128] = v1;
    d1[threadIdx.x] = v0; d1[threadIdx.x + 128] = v1;
}

// ---------------- GEMM core: C[M,N] = act(A[M,K] @ W[K,N] + bias) ----------------
// 128x128 tile, BK=16, 256 threads (8 warps as 4m x 2n), tf32 mma.sync, cp.async
// double buffered. A rows beyond M are zero-filled; stores guarded.
template <int K, int N, bool GELU>
__device__ __forceinline__ void gemm_core(const float* __restrict__ A,
                                          const float* __restrict__ W,
                                          const float* __restrict__ bias,
                                          float* __restrict__ C, int M) {
    __shared__ float As[2][128][20];   // [buf][row][k]  pitch 20 (conflict-free frag reads)
    __shared__ float Bs[2][16][136];   // [buf][k][n]    pitch 136 (conflict-free frag reads)

    const int tid  = threadIdx.x;
    const int lane = tid & 31;
    const int wid  = tid >> 5;
    const int wm   = wid >> 1;       // 0..3 -> 32 rows each
    const int wn   = wid & 1;        // 0..1 -> 64 cols each
    const int m0   = blockIdx.y * 128;
    const int n0   = blockIdx.x * 128;

    float acc[2][8][4];
#pragma unroll
    for (int a = 0; a < 2; a++)
#pragma unroll
        for (int b = 0; b < 8; b++)
#pragma unroll
            for (int c = 0; c < 4; c++) acc[a][b][c] = 0.f;

    // tile loaders
    const int ar = tid >> 2;            // 0..63
    const int akv = (tid & 3) * 4;      // 0,4,8,12
    const int bkr = tid >> 5;           // 0..7
    const int bnv = (tid & 31) * 4;     // 0..124

    auto load_tile = [&](int s, int it) {
        const int k0 = it * 16;
#pragma unroll
        for (int h = 0; h < 2; h++) {
            int row = ar + h * 64;
            bool p = (m0 + row) < M;
            const float* src = A + (size_t)(p ? (m0 + row) : 0) * K + k0 + akv;
            cpa16(&As[s][row][akv], src, p);
        }
#pragma unroll
        for (int h = 0; h < 2; h++) {
            int kk = bkr + h * 8;
            const float* src = W + (size_t)(k0 + kk) * N + n0 + bnv;
            cpa16(&Bs[s][kk][bnv], src, true);
        }
    };

    auto compute = [&](int s) {
#pragma unroll
        for (int ks = 0; ks < 2; ks++) {
            const int k0 = ks * 8;
            uint32_t af[2][4];
            uint32_t bf[8][2];
#pragma unroll
            for (int mt = 0; mt < 2; mt++) {
                int rb = wm * 32 + mt * 16 + (lane >> 2);
                int kk = k0 + (lane & 3);
                af[mt][0] = f2tf32(As[s][rb][kk]);
                af[mt][1] = f2tf32(As[s][rb + 8][kk]);
                af[mt][2] = f2tf32(As[s][rb][kk + 4]);
                af[mt][3] = f2tf32(As[s][rb + 8][kk + 4]);
            }
#pragma unroll
            for (int nt = 0; nt < 8; nt++) {
                int cb = wn * 64 + nt * 8 + (lane >> 2);
                bf[nt][0] = f2tf32(Bs[s][k0 + (lane & 3)][cb]);
                bf[nt][1] = f2tf32(Bs[s][k0 + 4 + (lane & 3)][cb]);
            }
#pragma unroll
            for (int mt = 0; mt < 2; mt++) {
#pragma unroll
                for (int nt = 0; nt < 8; nt++) {
                    asm volatile(
                        "mma.sync.aligned.m16n8k8.row.col.f32.tf32.tf32.f32 "
                        "{%0,%1,%2,%3}, {%4,%5,%6,%7}, {%8,%9}, {%0,%1,%2,%3};"
                        : "+f"(acc[mt][nt][0]), "+f"(acc[mt][nt][1]),
                          "+f"(acc[mt][nt][2]), "+f"(acc[mt][nt][3])
                        : "r"(af[mt][0]), "r"(af[mt][1]), "r"(af[mt][2]), "r"(af[mt][3]),
                          "r"(bf[nt][0]), "r"(bf[nt][1]));
                }
            }
        }
    };

    const int nk = K / 16;
    load_tile(0, 0);
    asm volatile("cp.async.commit_group;");
    for (int it = 0; it < nk; ++it) {
        if (it + 1 < nk) {
            load_tile((it + 1) & 1, it + 1);
            asm volatile("cp.async.commit_group;");
            asm volatile("cp.async.wait_group 1;");
        } else {
            asm volatile("cp.async.wait_group 0;");
        }
        __syncthreads();
        compute(it & 1);
        __syncthreads();
    }

    // epilogue
#pragma unroll
    for (int mt = 0; mt < 2; mt++) {
        int lr = wm * 32 + mt * 16 + (lane >> 2);
#pragma unroll
        for (int half = 0; half < 2; half++) {
            int row = lr + half * 8;
            if (m0 + row < M) {
                float* cp = C + (size_t)(m0 + row) * N + n0 + wn * 64 + (lane & 3) * 2;
                int cbase = n0 + wn * 64 + (lane & 3) * 2;
#pragma unroll
                for (int nt = 0; nt < 8; nt++) {
                    float v0 = acc[mt][nt][half * 2 + 0] + bias[cbase + nt * 8];
                    float v1 = acc[mt][nt][half * 2 + 1] + bias[cbase + nt * 8 + 1];
                    if (GELU) { v0 = gelu_exact(v0); v1 = gelu_exact(v1); }
                    float2 st; st.x = v0; st.y = v1;
                    *(float2*)(cp + nt * 8) = st;
                }
            }
        }
    }
}

__global__ void __launch_bounds__(256)
k_gemm1(const float* __restrict__ X, const float* __restrict__ W1,
        const float* __restrict__ b1, const float* __restrict__ sW1,
        const float* __restrict__ sb1) {
    const int z = blockIdx.z;
    int M; const float* A; const float* W; const float* bias; float* C;
    if (z < NEXP) {
        M = g_cnt[z];
        int base = g_off[z];
        A = g_Xg + (size_t)base * DIMSZ;
        W = W1 + (size_t)z * DIMSZ * INNER;
        bias = b1 + (size_t)z * INNER;
        C = g_H + (size_t)base * INNER;
    } else {
        M = T_TOK;
        A = X; W = sW1; bias = sb1;
        C = g_H + (size_t)2 * T_TOK * INNER;
    }
    if ((int)blockIdx.y * 128 >= M) return;
    gemm_core<DIMSZ, INNER, true>(A, W, bias, C, M);
}

__global__ void __launch_bounds__(256)
k_gemm2(const float* __restrict__ W2, const float* __restrict__ b2,
        const float* __restrict__ sW2, const float* __restrict__ sb2) {
    const int z = blockIdx.z;
    int M; const float* A; const float* W; const float* bias; float* C;
    if (z < NEXP) {
        M = g_cnt[z];
        int base = g_off[z];
        A = g_H + (size_t)base * INNER;
        W = W2 + (size_t)z * INNER * DIMSZ;
        bias = b2 + (size_t)z * DIMSZ;
        C = g_Og + (size_t)base * DIMSZ;
    } else {
        M = T_TOK;
        A = g_H + (size_t)2 * T_TOK * INNER;
        W = sW2; bias = sb2;
        C = g_Og + (size_t)2 * T_TOK * DIMSZ;
    }
    if ((int)blockIdx.y * 128 >= M) return;
    gemm_core<INNER, DIMSZ, false>(A, W, bias, C, M);
}

__global__ void k_combine(float* __restrict__ out) {
    int t = blockIdx.x;
    int r0 = g_rows[t * 2], r1 = g_rows[t * 2 + 1];
    float w0 = g_topw[t * 2], w1 = g_topw[t * 2 + 1];
    const float4* s = (const float4*)(g_Og + (size_t)(2 * T_TOK + t) * DIMSZ);
    const float4* a = (const float4*)(g_Og + (size_t)r0 * DIMSZ);
    const float4* b = (const float4*)(g_Og + (size_t)r1 * DIMSZ);
    float4* o = (float4*)(out + (size_t)t * DIMSZ);
    int i = threadIdx.x;  // 256 threads, 256 float4 per row
    float4 vs = s[i], va = a[i], vb = b[i];
    float4 r;
    r.x = vs.x + w0 * va.x + w1 * vb.x;
    r.y = vs.y + w0 * va.y + w1 * vb.y;
    r.z = vs.z + w0 * va.z + w1 * vb.z;
    r.w = vs.w + w0 * va.w + w1 * vb.w;
    o[i] = r;
}

// ---------------- launch ----------------
extern "C" void kernel_launch(void* const* d_in, const int* in_sizes, int n_in,
                              void* d_out, int out_size) {
    const float* x   = (const float*)d_in[0];
    const float* Wg  = (const float*)d_in[1];
    const float* W1  = (const float*)d_in[2];
    const float* b1  = (const float*)d_in[3];
    const float* W2  = (const float*)d_in[4];
    const float* b2  = (const float*)d_in[5];
    const float* sW1 = (const float*)d_in[6];
    const float* sb1 = (const float*)d_in[7];
    const float* sW2 = (const float*)d_in[8];
    const float* sb2 = (const float*)d_in[9];
    float* out = (float*)d_out;

    k_zero<<<1, 32>>>();
    k_gate<<<T_TOK / 4, 128>>>(x, Wg);
    k_scan<<<1, 1>>>();
    k_gather<<<T_TOK, 128>>>(x);

    dim3 g1(INNER / 128, T_TOK / 128, NEXP + 1);
    k_gemm1<<<g1, 256>>>(x, W1, b1, sW1, sb1);

    dim3 g2(DIMSZ / 128, T_TOK / 128, NEXP + 1);
    k_gemm2<<<g2, 256>>>(W2, b2, sW2, sb2);

    k_combine<<<T_TOK, 256>>>(out);
}

// round 7
// speedup vs baseline: 1.6057x; 1.6057x over previous
#include <cuda_runtime.h>
#include <cuda_fp16.h>
#include <cstdint>
#include <math.h>

// MoE block: gate -> gather -> fp16 HMMA GEMM1(+GELU) -> GEMM2 -> combine.
// All tensor math in fp16 inputs / fp32 accumulate (u=2^-11, same as tf32).

#define NTOK  4096
#define DMODEL 1024
#define DFFN  4096
#define NEXPERT 8

// ---------------- device scratch (static; no runtime allocation) ----------------
__device__ __half sc_Xg[2 * NTOK * DMODEL];         // gathered routed inputs (fp16)
__device__ __half sc_Xr[NTOK * DMODEL];             // fp16 copy of X (shared expert)
__device__ __half sc_H [3 * NTOK * DFFN];           // hidden activations (fp16)
__device__ float  sc_O [3 * NTOK * DMODEL];         // ffn outputs (fp32)
__device__ __half sc_W1t[NEXPERT * DFFN * DMODEL];  // W1^T fp16: [n(DFFN), k(DMODEL)]
__device__ __half sc_W2t[NEXPERT * DMODEL * DFFN];  // W2^T fp16: [n(DMODEL), k(DFFN)]
__device__ __half sc_sW1t[DFFN * DMODEL];
__device__ __half sc_sW2t[DMODEL * DFFN];
__device__ float sc_topw[NTOK * 2];
__device__ int   sc_tope[NTOK * 2];
__device__ int   sc_rows[NTOK * 2];
__device__ int   sc_cnt[NEXPERT];
__device__ int   sc_cur[NEXPERT];
__device__ int   sc_off[NEXPERT];

// ---------------- helpers ----------------
__device__ __forceinline__ void cp_async16(uint32_t saddr, const void* g, bool p) {
    int sz = p ? 16 : 0;
    asm volatile("cp.async.cg.shared.global [%0], [%1], 16, %2;\n"
                 :: "r"(saddr), "l"(g), "r"(sz));
}

__device__ __forceinline__ float gelu_erf(float v) {
    return 0.5f * v * (1.0f + erff(v * 0.70710678118654752440f));
}

// ---------------- routing kernels ----------------
__global__ void kRouteInit() {
    int i = threadIdx.x;
    if (i < NEXPERT) { sc_cnt[i] = 0; sc_cur[i] = 0; }
}

__global__ void kRouteGate(const float* __restrict__ x, const float* __restrict__ Wg) {
    int t = blockIdx.x * 4 + (threadIdx.x >> 5);
    int lane = threadIdx.x & 31;
    if (t >= NTOK) return;
    const float* xp = x + (size_t)t * DMODEL;
    float xr[32];
#pragma unroll
    for (int j = 0; j < 32; j++) xr[j] = xp[j * 32 + lane];
    float s[NEXPERT];
#pragma unroll
    for (int e = 0; e < NEXPERT; e++) {
        const float* wg = Wg + e * DMODEL;
        float p = 0.f;
#pragma unroll
        for (int j = 0; j < 32; j++) p += xr[j] * wg[j * 32 + lane];
#pragma unroll
        for (int o = 16; o > 0; o >>= 1) p += __shfl_xor_sync(0xffffffffu, p, o);
        s[e] = p;
    }
    if (lane == 0) {
        float m = s[0];
#pragma unroll
        for (int e = 1; e < NEXPERT; e++) m = fmaxf(m, s[e]);
        float p[NEXPERT]; float sum = 0.f;
#pragma unroll
        for (int e = 0; e < NEXPERT; e++) { p[e] = expf(s[e] - m); sum += p[e]; }
        float inv = 1.0f / sum;
#pragma unroll
        for (int e = 0; e < NEXPERT; e++) p[e] *= inv;
        int e0 = 0; float w0 = p[0];
#pragma unroll
        for (int e = 1; e < NEXPERT; e++) if (p[e] > w0) { w0 = p[e]; e0 = e; }
        int e1 = -1; float w1 = -1.f;
#pragma unroll
        for (int e = 0; e < NEXPERT; e++) if (e != e0 && p[e] > w1) { w1 = p[e]; e1 = e; }
        sc_topw[t * 2] = w0;     sc_tope[t * 2] = e0;
        sc_topw[t * 2 + 1] = w1; sc_tope[t * 2 + 1] = e1;
        atomicAdd(&sc_cnt[e0], 1);
        atomicAdd(&sc_cnt[e1], 1);
    }
}

__global__ void kRouteScan() {
    if (threadIdx.x == 0) {
        int acc = 0;
        for (int e = 0; e < NEXPERT; e++) { sc_off[e] = acc; acc += sc_cnt[e]; }
    }
}

__global__ void kRouteGather(const float* __restrict__ x) {
    int t = blockIdx.x;
    __shared__ int rs[2];
    if (threadIdx.x == 0) {
#pragma unroll
        for (int k = 0; k < 2; k++) {
            int e = sc_tope[t * 2 + k];
            int slot = atomicAdd(&sc_cur[e], 1);
            int r = sc_off[e] + slot;
            sc_rows[t * 2 + k] = r;
            rs[k] = r;
        }
    }
    __syncthreads();
    const float4* xp = (const float4*)(x + (size_t)t * DMODEL);
#pragma unroll
    for (int h = 0; h < 2; h++) {
        float4 v = xp[threadIdx.x + h * 128];
        __half2 h0 = __floats2half2_rn(v.x, v.y);
        __half2 h1 = __floats2half2_rn(v.z, v.w);
        uint2 pk = make_uint2(*(uint32_t*)&h0, *(uint32_t*)&h1);
        int idx = threadIdx.x + h * 128;            // 8B unit index within a row
        ((uint2*)(sc_Xr + (size_t)t * DMODEL))[idx] = pk;
        ((uint2*)(sc_Xg + (size_t)rs[0] * DMODEL))[idx] = pk;
        ((uint2*)(sc_Xg + (size_t)rs[1] * DMODEL))[idx] = pk;
    }
}

// ---------------- weight transpose + fp16 convert ----------------
// src [K,N] fp32 row-major -> dst [N,K] fp16 row-major
__global__ void kWeightPrep(const float* __restrict__ W1, const float* __restrict__ W2,
                            const float* __restrict__ sW1, const float* __restrict__ sW2) {
    __shared__ float tb[32][33];
    int z = blockIdx.z;
    const float* src; __half* dst; int K, N, kb, nb;
    if (z < 8) {
        src = W1 + (size_t)z * DMODEL * DFFN; dst = sc_W1t + (size_t)z * DFFN * DMODEL;
        K = DMODEL; N = DFFN; kb = blockIdx.x; nb = blockIdx.y;
    } else if (z < 16) {
        int e = z - 8;
        src = W2 + (size_t)e * DFFN * DMODEL; dst = sc_W2t + (size_t)e * DMODEL * DFFN;
        K = DFFN; N = DMODEL; kb = blockIdx.y; nb = blockIdx.x;
    } else if (z == 16) {
        src = sW1; dst = sc_sW1t; K = DMODEL; N = DFFN; kb = blockIdx.x; nb = blockIdx.y;
    } else {
        src = sW2; dst = sc_sW2t; K = DFFN; N = DMODEL; kb = blockIdx.y; nb = blockIdx.x;
    }
    int tx = threadIdx.x, ty = threadIdx.y;
#pragma unroll
    for (int i = 0; i < 4; i++) {
        int k = kb * 32 + ty + i * 8;
        int n = nb * 32 + tx;
        tb[ty + i * 8][tx] = src[(size_t)k * N + n];
    }
    __syncthreads();
#pragma unroll
    for (int i = 0; i < 4; i++) {
        int n = nb * 32 + ty + i * 8;
        int k = kb * 32 + tx;
        dst[(size_t)n * K + k] = __float2half_rn(tb[tx][ty + i * 8]);
    }
}

// ---------------- fp16 mma GEMM core ----------------
// C[M,NOUT] = act(A[M,K] @ B^T + bias). A fp16 [M][K]; B fp16 [NOUT][K] (=W^T).
// 128x128 block, BK=32, 8 warps (4m x 2n), m16n8k16 fp16 HMMA, fp32 accumulate,
// cp.async double buffer.
template <int K, int NOUT, bool GELU, typename CT>
__device__ __forceinline__ void gemm_fp16(const __half* __restrict__ A,
                                          const __half* __restrict__ B,
                                          const float* __restrict__ bias,
                                          CT* __restrict__ C, int M) {
    __shared__ __half As[2][128][40];   // pitch 40 halves (80B)
    __shared__ __half Bs[2][128][40];

    const int tid  = threadIdx.x;
    const int lane = tid & 31;
    const int wid  = tid >> 5;
    const int wm   = wid >> 1;       // 0..3 -> 32 rows each
    const int wn   = wid & 1;        // 0..1 -> 64 cols each
    const int m0   = blockIdx.y * 128;
    const int n0   = blockIdx.x * 128;
    if (m0 >= M) return;

    float acc[2][8][4];
#pragma unroll
    for (int a = 0; a < 2; a++)
#pragma unroll
        for (int b = 0; b < 8; b++)
#pragma unroll
            for (int c = 0; c < 4; c++) acc[a][b][c] = 0.f;

    // staging: per operand 128 rows x 64B = 512 x 16B chunks; 256 threads -> 2 each
    auto load_tile = [&](int s, int it) {
        const int k0 = it * 32;                       // in halves
#pragma unroll
        for (int h = 0; h < 2; h++) {
            int chunk = tid + h * 256;
            int row = chunk >> 2;                     // 0..127
            int co  = (chunk & 3) * 8;                // halves offset in row
            bool p = (m0 + row) < M;
            const __half* srcA = A + (size_t)(p ? (m0 + row) : 0) * K + k0 + co;
            cp_async16((uint32_t)__cvta_generic_to_shared(&As[s][row][co]), srcA, p);
            const __half* srcB = B + (size_t)(n0 + row) * K + k0 + co;
            cp_async16((uint32_t)__cvta_generic_to_shared(&Bs[s][row][co]), srcB, true);
        }
    };

    auto compute = [&](int s) {
#pragma unroll
        for (int ks = 0; ks < 2; ks++) {
            const int kk = ks * 16 + 2 * (lane & 3);
            uint32_t af[2][4];
            uint32_t bf[8][2];
#pragma unroll
            for (int mt = 0; mt < 2; mt++) {
                int rb = wm * 32 + mt * 16 + (lane >> 2);
                af[mt][0] = *(const uint32_t*)&As[s][rb][kk];
                af[mt][1] = *(const uint32_t*)&As[s][rb + 8][kk];
                af[mt][2] = *(const uint32_t*)&As[s][rb][kk + 8];
                af[mt][3] = *(const uint32_t*)&As[s][rb + 8][kk + 8];
            }
#pragma unroll
            for (int nt = 0; nt < 8; nt++) {
                int nb = wn * 64 + nt * 8 + (lane >> 2);
                bf[nt][0] = *(const uint32_t*)&Bs[s][nb][kk];
                bf[nt][1] = *(const uint32_t*)&Bs[s][nb][kk + 8];
            }
#pragma unroll
            for (int mt = 0; mt < 2; mt++) {
#pragma unroll
                for (int nt = 0; nt < 8; nt++) {
                    asm volatile(
                        "mma.sync.aligned.m16n8k16.row.col.f32.f16.f16.f32 "
                        "{%0,%1,%2,%3}, {%4,%5,%6,%7}, {%8,%9}, {%0,%1,%2,%3};"
                        : "+f"(acc[mt][nt][0]), "+f"(acc[mt][nt][1]),
                          "+f"(acc[mt][nt][2]), "+f"(acc[mt][nt][3])
                        : "r"(af[mt][0]), "r"(af[mt][1]), "r"(af[mt][2]), "r"(af[mt][3]),
                          "r"(bf[nt][0]), "r"(bf[nt][1]));
                }
            }
        }
    };

    const int nk = K / 32;
    load_tile(0, 0);
    asm volatile("cp.async.commit_group;");
    for (int it = 0; it < nk; ++it) {
        if (it + 1 < nk) {
            load_tile((it + 1) & 1, it + 1);
            asm volatile("cp.async.commit_group;");
            asm volatile("cp.async.wait_group 1;");
        } else {
            asm volatile("cp.async.wait_group 0;");
        }
        __syncthreads();
        compute(it & 1);
        __syncthreads();
    }

    // epilogue: acc[c0,c1] -> (row, col..col+1); acc[c2,c3] -> row+8
#pragma unroll
    for (int mt = 0; mt < 2; mt++) {
        int rbase = m0 + wm * 32 + mt * 16 + (lane >> 2);
#pragma unroll
        for (int half = 0; half < 2; half++) {
            int row = rbase + half * 8;
            if (row < M) {
#pragma unroll
                for (int nt = 0; nt < 8; nt++) {
                    int col = n0 + wn * 64 + nt * 8 + 2 * (lane & 3);
                    float v0 = acc[mt][nt][half * 2 + 0] + bias[col];
                    float v1 = acc[mt][nt][half * 2 + 1] + bias[col + 1];
                    if (GELU) { v0 = gelu_erf(v0); v1 = gelu_erf(v1); }
                    CT* cp = C + (size_t)row * NOUT + col;
                    if (sizeof(CT) == 2) {
                        __half2 hv = __floats2half2_rn(v0, v1);
                        *(__half2*)cp = hv;
                    } else {
                        float2 fv; fv.x = v0; fv.y = v1;
                        *(float2*)cp = fv;
                    }
                }
            }
        }
    }
}

__global__ void __launch_bounds__(256)
kFfn1(const float* __restrict__ b1, const float* __restrict__ sb1) {
    const int z = blockIdx.z;
    int M; const __half* A; const __half* B; const float* bias; __half* C;
    if (z < NEXPERT) {
        M = sc_cnt[z];
        int base = sc_off[z];
        A = sc_Xg + (size_t)base * DMODEL;
        B = sc_W1t + (size_t)z * DFFN * DMODEL;
        bias = b1 + (size_t)z * DFFN;
        C = sc_H + (size_t)base * DFFN;
    } else {
        M = NTOK; A = sc_Xr; B = sc_sW1t; bias = sb1;
        C = sc_H + (size_t)2 * NTOK * DFFN;
    }
    gemm_fp16<DMODEL, DFFN, true, __half>(A, B, bias, C, M);
}

__global__ void __launch_bounds__(256)
kFfn2(const float* __restrict__ b2, const float* __restrict__ sb2) {
    const int z = blockIdx.z;
    int M; const __half* A; const __half* B; const float* bias; float* C;
    if (z < NEXPERT) {
        M = sc_cnt[z];
        int base = sc_off[z];
        A = sc_H + (size_t)base * DFFN;
        B = sc_W2t + (size_t)z * DMODEL * DFFN;
        bias = b2 + (size_t)z * DMODEL;
        C = sc_O + (size_t)base * DMODEL;
    } else {
        M = NTOK;
        A = sc_H + (size_t)2 * NTOK * DFFN;
        B = sc_sW2t; bias = sb2;
        C = sc_O + (size_t)2 * NTOK * DMODEL;
    }
    gemm_fp16<DFFN, DMODEL, false, float>(A, B, bias, C, M);
}

__global__ void kCombine(float* __restrict__ out) {
    int t = blockIdx.x;
    int r0 = sc_rows[t * 2], r1 = sc_rows[t * 2 + 1];
    float w0 = sc_topw[t * 2], w1 = sc_topw[t * 2 + 1];
    const float4* s = (const float4*)(sc_O + (size_t)(2 * NTOK + t) * DMODEL);
    const float4* a = (const float4*)(sc_O + (size_t)r0 * DMODEL);
    const float4* b = (const float4*)(sc_O + (size_t)r1 * DMODEL);
    float4* o = (float4*)(out + (size_t)t * DMODEL);
    int i = threadIdx.x;
    float4 vs = s[i], va = a[i], vb = b[i];
    float4 r;
    r.x = vs.x + w0 * va.x + w1 * vb.x;
    r.y = vs.y + w0 * va.y + w1 * vb.y;
    r.z = vs.z + w0 * va.z + w1 * vb.z;
    r.w = vs.w + w0 * va.w + w1 * vb.w;
    o[i] = r;
}

// ---------------- launch ----------------
extern "C" void kernel_launch(void* const* d_in, const int* in_sizes, int n_in,
                              void* d_out, int out_size) {
    const float* x   = (const float*)d_in[0];
    const float* Wg  = (const float*)d_in[1];
    const float* W1  = (const float*)d_in[2];
    const float* b1  = (const float*)d_in[3];
    const float* W2  = (const float*)d_in[4];
    const float* b2  = (const float*)d_in[5];
    const float* sW1 = (const float*)d_in[6];
    const float* sb1 = (const float*)d_in[7];
    const float* sW2 = (const float*)d_in[8];
    const float* sb2 = (const float*)d_in[9];
    float* out = (float*)d_out;

    kRouteInit<<<1, 32>>>();
    kRouteGate<<<NTOK / 4, 128>>>(x, Wg);
    kRouteScan<<<1, 1>>>();
    kRouteGather<<<NTOK, 128>>>(x);

    dim3 tg(32, 128, 18);
    kWeightPrep<<<tg, dim3(32, 8)>>>(W1, W2, sW1, sW2);

    dim3 g1(DFFN / 128, NTOK / 128, NEXPERT + 1);
    kFfn1<<<g1, 256>>>(b1, sb1);

    dim3 g2(DMODEL / 128, NTOK / 128, NEXPERT + 1);
    kFfn2<<<g2, 256>>>(b2, sb2);

    kCombine<<<NTOK, 256>>>(out);
}